// round 12
// baseline (speedup 1.0000x reference)
#include <cuda_runtime.h>

// RAPiD box decode (held steady — no bench has ever run; broker timeouts only):
//  raw: (64, 18, 128, 128) f32, 18 = 3 anchors * 6 channels (x,y,w,h,angle,conf)
//  out: (64, 3*128*128, 6) f32
//  px = (sigmoid(x)+wx)/nW*img_w ; py = (sigmoid(y)+wy)/nH*img_h
//  pw = exp(w)*anch_w ; ph = exp(h)*anch_h
//  pa = sigmoid(a)*360-180 ; conf = sigmoid(c)
//
// One thread handles 4 adjacent w positions:
//  - 6 float4 coalesced plane reads (LDG.E.128.CS, MLP=6)
//  - 24 contiguous output floats = 6 float4 streaming stores (96 B/thread)
// All data is single-use (151 MB > 126 MB L2), so evict-first hints on both
// sides: nothing to keep in L2.

#define NB 64
#define NA 3
#define NH 128
#define NW 128
#define PLANE (NH * NW)          // 16384

__device__ __forceinline__ float sigm(float x) {
    // MUFU path: EX2 + RCP. rel err ~2^-21, well under 1e-3 tolerance.
    return __fdividef(1.0f, 1.0f + __expf(-x));
}

// Dtype-agnostic scalar read: the harness may materialize python-int scalars
// as int32 or float32. An image dimension is < 2^20; a float-encoded one
// read as int is huge (1024.0f -> 0x44800000). Disambiguate on magnitude.
__device__ __forceinline__ float scalar_as_float(const void* p) {
    unsigned u = *(const unsigned*)p;
    if (u <= (1u << 20)) return (float)(int)u;    // plain int32
    return __uint_as_float(u);                     // float32 bits
}

__global__ void __launch_bounds__(256) rapid_decode_kernel(
    const float* __restrict__ raw,
    const float* __restrict__ anchors,
    const void*  __restrict__ img_h_p,
    const void*  __restrict__ img_w_p,
    float* __restrict__ out)
{
    // total threads = NB * NA * NH * (NW/4) = 786,432
    int t = blockIdx.x * blockDim.x + threadIdx.x;
    int wq = t & 31;                 // quad index along w (0..31)
    int h  = (t >> 5) & 127;
    int ba = t >> 12;                // b*3 + a, 0..191
    int a  = ba - (ba / NA) * NA;

    int w0 = wq << 2;

    float sx = scalar_as_float(img_w_p) * (1.0f / (float)NW);   // 8.0
    float sy = scalar_as_float(img_h_p) * (1.0f / (float)NH);   // 8.0
    float aw = __ldg(&anchors[a * 2 + 0]);
    float ah = __ldg(&anchors[a * 2 + 1]);

    // input base: raw[b][a*6 + 0][h][w0]; b*18 + a*6 == ba*6
    const float* base = raw + (((ba * 6) * NH + h) * NW + w0);

    float4 vx = __ldcs((const float4*)(base + 0 * PLANE));
    float4 vy = __ldcs((const float4*)(base + 1 * PLANE));
    float4 vw = __ldcs((const float4*)(base + 2 * PLANE));
    float4 vh = __ldcs((const float4*)(base + 3 * PLANE));
    float4 va = __ldcs((const float4*)(base + 4 * PLANE));
    float4 vc = __ldcs((const float4*)(base + 5 * PLANE));

    float fw0 = (float)w0;
    float fh  = (float)h;

    float pyc0 = (sigm(vy.x) + fh) * sy;
    float pyc1 = (sigm(vy.y) + fh) * sy;
    float pyc2 = (sigm(vy.z) + fh) * sy;
    float pyc3 = (sigm(vy.w) + fh) * sy;

    float px0 = (sigm(vx.x) + fw0)        * sx;
    float px1 = (sigm(vx.y) + fw0 + 1.0f) * sx;
    float px2 = (sigm(vx.z) + fw0 + 2.0f) * sx;
    float px3 = (sigm(vx.w) + fw0 + 3.0f) * sx;

    float pw0 = __expf(vw.x) * aw;
    float pw1 = __expf(vw.y) * aw;
    float pw2 = __expf(vw.z) * aw;
    float pw3 = __expf(vw.w) * aw;

    float ph0 = __expf(vh.x) * ah;
    float ph1 = __expf(vh.y) * ah;
    float ph2 = __expf(vh.z) * ah;
    float ph3 = __expf(vh.w) * ah;

    float pa0 = sigm(va.x) * 360.0f - 180.0f;
    float pa1 = sigm(va.y) * 360.0f - 180.0f;
    float pa2 = sigm(va.z) * 360.0f - 180.0f;
    float pa3 = sigm(va.w) * 360.0f - 180.0f;

    float c0 = sigm(vc.x);
    float c1 = sigm(vc.y);
    float c2 = sigm(vc.z);
    float c3 = sigm(vc.w);

    // output position: ((b*3+a)*16384 + h*128 + w0) * 6 ; w0%4==0 -> *24 floats -> 96B aligned
    int opos = ((ba * PLANE) + h * NW + w0) * 6;
    float4* o = (float4*)(out + opos);
    __stcs(o + 0, make_float4(px0, pyc0, pw0, ph0));
    __stcs(o + 1, make_float4(pa0, c0,  px1, pyc1));
    __stcs(o + 2, make_float4(pw1, ph1, pa1, c1));
    __stcs(o + 3, make_float4(px2, pyc2, pw2, ph2));
    __stcs(o + 4, make_float4(pa2, c2,  px3, pyc3));
    __stcs(o + 5, make_float4(pw3, ph3, pa3, c3));
}

extern "C" void kernel_launch(void* const* d_in, const int* in_sizes, int n_in,
                              void* d_out, int out_size)
{
    const float* raw     = (const float*)d_in[0];
    const float* anchors = (const float*)d_in[1];
    const void*  img_h   = d_in[2];
    const void*  img_w   = d_in[3];
    float*       out     = (float*)d_out;

    const int total = NB * NA * NH * (NW / 4);   // 786,432
    const int block = 256;
    const int grid  = (total + block - 1) / block;  // 3072
    rapid_decode_kernel<<<grid, block>>>(raw, anchors, img_h, img_w, out);
}